// round 1
// baseline (speedup 1.0000x reference)
#include <cuda_runtime.h>
#include <math.h>
#include <stdint.h>

#define BB 2
#define TT 2048
#define DD 2048
#define HH 16
#define HKK 4
#define HDD 128
#define REP 4
#define ROWS (BB*TT)   // 4096

// Scratch (no cudaMalloc allowed)
__device__ float g_q[(size_t)ROWS*HH*HDD];    // 32MB
__device__ float g_k[(size_t)ROWS*HKK*HDD];   // 8MB
__device__ float g_v[(size_t)ROWS*HKK*HDD];   // 8MB
__device__ float g_att[(size_t)ROWS*HH*HDD];  // 32MB

// ---------------------------------------------------------------------------
// SGEMM: C[M,N] = A[M,K] @ B[K,N], all row-major, fp32.
// BM=128, BN=128, BK=16, 256 threads, 8x8 per thread. Dims assumed divisible.
// ---------------------------------------------------------------------------
#define BM 128
#define BN 128
#define BKK 16
#define TM 8
#define TN 8
#define ASTRIDE (BM + 4)   // padded to cut transposed-store bank conflicts

__global__ void __launch_bounds__(256, 2) sgemm_kernel(
    int M, int N, int K,
    const float* __restrict__ A, const float* __restrict__ B, float* __restrict__ C)
{
    __shared__ float As[BKK * ASTRIDE];
    __shared__ float Bs[BKK * BN];

    const int tid = threadIdx.x;
    const int tx = tid & 15;        // 0..15 (col group)
    const int ty = tid >> 4;        // 0..15 (row group)
    const int rowBase = blockIdx.y * BM;
    const int colBase = blockIdx.x * BN;

    float acc[TM][TN];
    #pragma unroll
    for (int i = 0; i < TM; i++)
        #pragma unroll
        for (int j = 0; j < TN; j++) acc[i][j] = 0.0f;

    for (int k0 = 0; k0 < K; k0 += BKK) {
        // Load A tile (BM x BK) -> transposed smem As[k][m]
        #pragma unroll
        for (int n = 0; n < (BM * BKK) / (256 * 4); n++) {   // 2 iters
            int idx = tid + n * 256;
            int r  = idx >> 2;           // 0..127
            int c4 = idx & 3;            // 0..3
            float4 a = *reinterpret_cast<const float4*>(
                &A[(size_t)(rowBase + r) * K + k0 + c4 * 4]);
            As[(c4 * 4 + 0) * ASTRIDE + r] = a.x;
            As[(c4 * 4 + 1) * ASTRIDE + r] = a.y;
            As[(c4 * 4 + 2) * ASTRIDE + r] = a.z;
            As[(c4 * 4 + 3) * ASTRIDE + r] = a.w;
        }
        // Load B tile (BK x BN) direct
        #pragma unroll
        for (int n = 0; n < (BKK * BN) / (256 * 4); n++) {   // 2 iters
            int idx = tid + n * 256;
            int r  = idx >> 5;           // 0..15
            int c4 = idx & 31;           // 0..31
            *reinterpret_cast<float4*>(&Bs[r * BN + c4 * 4]) =
                *reinterpret_cast<const float4*>(
                    &B[(size_t)(k0 + r) * N + colBase + c4 * 4]);
        }
        __syncthreads();

        #pragma unroll
        for (int kk = 0; kk < BKK; kk++) {
            float a[TM], b[TN];
            float4 av0 = *reinterpret_cast<const float4*>(&As[kk * ASTRIDE + ty * TM]);
            float4 av1 = *reinterpret_cast<const float4*>(&As[kk * ASTRIDE + ty * TM + 4]);
            float4 bv0 = *reinterpret_cast<const float4*>(&Bs[kk * BN + tx * TN]);
            float4 bv1 = *reinterpret_cast<const float4*>(&Bs[kk * BN + tx * TN + 4]);
            a[0]=av0.x; a[1]=av0.y; a[2]=av0.z; a[3]=av0.w;
            a[4]=av1.x; a[5]=av1.y; a[6]=av1.z; a[7]=av1.w;
            b[0]=bv0.x; b[1]=bv0.y; b[2]=bv0.z; b[3]=bv0.w;
            b[4]=bv1.x; b[5]=bv1.y; b[6]=bv1.z; b[7]=bv1.w;
            #pragma unroll
            for (int i = 0; i < TM; i++)
                #pragma unroll
                for (int j = 0; j < TN; j++)
                    acc[i][j] = fmaf(a[i], b[j], acc[i][j]);
        }
        __syncthreads();
    }

    #pragma unroll
    for (int i = 0; i < TM; i++) {
        size_t r = (size_t)(rowBase + ty * TM + i) * N + colBase + tx * TN;
        *reinterpret_cast<float4*>(&C[r])     = make_float4(acc[i][0], acc[i][1], acc[i][2], acc[i][3]);
        *reinterpret_cast<float4*>(&C[r + 4]) = make_float4(acc[i][4], acc[i][5], acc[i][6], acc[i][7]);
    }
}

// ---------------------------------------------------------------------------
// RoPE (interleaved pairs): x[row, h, 2i], x[row, h, 2i+1]
// ---------------------------------------------------------------------------
__global__ void rope_kernel(float* __restrict__ x,
                            const float* __restrict__ cs,
                            const float* __restrict__ sn, int nh, int total)
{
    int idx = blockIdx.x * blockDim.x + threadIdx.x;
    if (idx >= total) return;
    int i    = idx % (HDD / 2);
    int rest = idx / (HDD / 2);
    int h    = rest % nh;
    int row  = rest / nh;
    int t    = row % TT;
    float c = cs[t * (HDD / 2) + i];
    float s = sn[t * (HDD / 2) + i];
    float* p = x + ((size_t)row * nh + h) * HDD + 2 * i;
    float xr = p[0], xi = p[1];
    p[0] = xr * c - xi * s;
    p[1] = xr * s + xi * c;
}

// ---------------------------------------------------------------------------
// Flash attention fp32, causal. Br=Bc=64, 256 threads (16x16, 4x4 S-tile each).
// Qs/Ks stored transposed [d][i] with stride 68; Vs natural [s][d]; Ps [kk][i].
// ---------------------------------------------------------------------------
#define BR 64
#define BC 64
#define QS 68
#define FLASH_SMEM ((HDD*QS + HDD*QS + BC*QS + BC*HDD) * sizeof(float))  // 119808 B

__global__ void __launch_bounds__(256, 1) flash_kernel(
    const float* __restrict__ q, const float* __restrict__ k,
    const float* __restrict__ v, float* __restrict__ att)
{
    extern __shared__ float sm[];
    float* Qs = sm;                 // [HD][QS]
    float* Ks = Qs + HDD * QS;      // [HD][QS]
    float* Ps = Ks + HDD * QS;      // [BC][QS]
    float* Vs = Ps + BC * QS;       // [BC][HD]

    const int tid = threadIdx.x;
    const int tx = tid & 15;
    const int ty = tid >> 4;
    const int qt = blockIdx.x;
    const int h  = blockIdx.y;
    const int b  = blockIdx.z;
    const int hk = h / REP;
    const int qrow0 = qt * BR;
    const float scale = 0.08838834764831845f;  // 1/sqrt(128)

    // Load Q tile transposed
    {
        const float* qbase = q + ((size_t)(b * TT + qrow0) * HH + h) * HDD;
        #pragma unroll
        for (int n = 0; n < (BR * HDD) / (256 * 4); n++) {   // 8 iters
            int idx = tid + n * 256;
            int r  = idx >> 5;          // 0..63
            int d4 = idx & 31;          // 0..31
            float4 val = *reinterpret_cast<const float4*>(qbase + (size_t)r * HH * HDD + d4 * 4);
            Qs[(d4 * 4 + 0) * QS + r] = val.x;
            Qs[(d4 * 4 + 1) * QS + r] = val.y;
            Qs[(d4 * 4 + 2) * QS + r] = val.z;
            Qs[(d4 * 4 + 3) * QS + r] = val.w;
        }
    }

    float m[4], l[4], o[4][8];
    #pragma unroll
    for (int r = 0; r < 4; r++) {
        m[r] = -INFINITY; l[r] = 0.0f;
        #pragma unroll
        for (int c = 0; c < 8; c++) o[r][c] = 0.0f;
    }

    const int ntiles = qt + 1;   // causal
    for (int kt = 0; kt < ntiles; kt++) {
        __syncthreads();   // protect Ks/Vs/Ps from previous iteration readers
        // Load K (transposed) and V (natural)
        {
            const float* kbase = k + ((size_t)(b * TT + kt * BC) * HKK + hk) * HDD;
            const float* vbase = v + ((size_t)(b * TT + kt * BC) * HKK + hk) * HDD;
            #pragma unroll
            for (int n = 0; n < (BC * HDD) / (256 * 4); n++) {   // 8 iters
                int idx = tid + n * 256;
                int r  = idx >> 5;
                int d4 = idx & 31;
                float4 kv = *reinterpret_cast<const float4*>(kbase + (size_t)r * HKK * HDD + d4 * 4);
                Ks[(d4 * 4 + 0) * QS + r] = kv.x;
                Ks[(d4 * 4 + 1) * QS + r] = kv.y;
                Ks[(d4 * 4 + 2) * QS + r] = kv.z;
                Ks[(d4 * 4 + 3) * QS + r] = kv.w;
                float4 vv = *reinterpret_cast<const float4*>(vbase + (size_t)r * HKK * HDD + d4 * 4);
                *reinterpret_cast<float4*>(&Vs[r * HDD + d4 * 4]) = vv;
            }
        }
        __syncthreads();

        // S = Q K^T (4x4 per thread)
        float s[4][4];
        #pragma unroll
        for (int r = 0; r < 4; r++)
            #pragma unroll
            for (int c = 0; c < 4; c++) s[r][c] = 0.0f;

        #pragma unroll 4
        for (int d = 0; d < HDD; d++) {
            float4 av = *reinterpret_cast<const float4*>(&Qs[d * QS + ty * 4]);
            float4 bv = *reinterpret_cast<const float4*>(&Ks[d * QS + tx * 4]);
            float a0 = av.x, a1 = av.y, a2 = av.z, a3 = av.w;
            float b0 = bv.x, b1 = bv.y, b2 = bv.z, b3 = bv.w;
            s[0][0] = fmaf(a0,b0,s[0][0]); s[0][1] = fmaf(a0,b1,s[0][1]);
            s[0][2] = fmaf(a0,b2,s[0][2]); s[0][3] = fmaf(a0,b3,s[0][3]);
            s[1][0] = fmaf(a1,b0,s[1][0]); s[1][1] = fmaf(a1,b1,s[1][1]);
            s[1][2] = fmaf(a1,b2,s[1][2]); s[1][3] = fmaf(a1,b3,s[1][3]);
            s[2][0] = fmaf(a2,b0,s[2][0]); s[2][1] = fmaf(a2,b1,s[2][1]);
            s[2][2] = fmaf(a2,b2,s[2][2]); s[2][3] = fmaf(a2,b3,s[2][3]);
            s[3][0] = fmaf(a3,b0,s[3][0]); s[3][1] = fmaf(a3,b1,s[3][1]);
            s[3][2] = fmaf(a3,b2,s[3][2]); s[3][3] = fmaf(a3,b3,s[3][3]);
        }

        // scale + causal mask (only needed on diagonal tile)
        if (kt == qt) {
            #pragma unroll
            for (int r = 0; r < 4; r++) {
                int qr = qrow0 + ty * 4 + r;
                #pragma unroll
                for (int c = 0; c < 4; c++) {
                    int kc = kt * BC + tx * 4 + c;
                    s[r][c] = (kc <= qr) ? s[r][c] * scale : -INFINITY;
                }
            }
        } else {
            #pragma unroll
            for (int r = 0; r < 4; r++)
                #pragma unroll
                for (int c = 0; c < 4; c++) s[r][c] *= scale;
        }

        // online softmax
        #pragma unroll
        for (int r = 0; r < 4; r++) {
            float mx = fmaxf(fmaxf(s[r][0], s[r][1]), fmaxf(s[r][2], s[r][3]));
            #pragma unroll
            for (int off = 8; off >= 1; off >>= 1)
                mx = fmaxf(mx, __shfl_xor_sync(0xffffffffu, mx, off, 16));
            float nm = fmaxf(m[r], mx);            // finite: col kt*64 always visible
            float alpha = __expf(m[r] - nm);       // 0 when m==-inf
            float ps = 0.0f;
            #pragma unroll
            for (int c = 0; c < 4; c++) {
                float e = __expf(s[r][c] - nm);
                s[r][c] = e;
                ps += e;
            }
            #pragma unroll
            for (int off = 8; off >= 1; off >>= 1)
                ps += __shfl_xor_sync(0xffffffffu, ps, off, 16);
            l[r] = l[r] * alpha + ps;
            m[r] = nm;
            #pragma unroll
            for (int c = 0; c < 8; c++) o[r][c] *= alpha;
            // store P transposed: Ps[kk][i]
            #pragma unroll
            for (int c = 0; c < 4; c++)
                Ps[(tx * 4 + c) * QS + ty * 4 + r] = s[r][c];
        }
        __syncthreads();

        // O += P @ V
        #pragma unroll 2
        for (int kk = 0; kk < BC; kk++) {
            float4 pv = *reinterpret_cast<const float4*>(&Ps[kk * QS + ty * 4]);
            float p0 = pv.x, p1 = pv.y, p2 = pv.z, p3 = pv.w;
            float4 v0 = *reinterpret_cast<const float4*>(&Vs[kk * HDD + tx * 8]);
            float4 v1 = *reinterpret_cast<const float4*>(&Vs[kk * HDD + tx * 8 + 4]);
            float vv[8] = {v0.x, v0.y, v0.z, v0.w, v1.x, v1.y, v1.z, v1.w};
            #pragma unroll
            for (int c = 0; c < 8; c++) {
                o[0][c] = fmaf(p0, vv[c], o[0][c]);
                o[1][c] = fmaf(p1, vv[c], o[1][c]);
                o[2][c] = fmaf(p2, vv[c], o[2][c]);
                o[3][c] = fmaf(p3, vv[c], o[3][c]);
            }
        }
    }

    // epilogue
    #pragma unroll
    for (int r = 0; r < 4; r++) {
        float inv = 1.0f / l[r];
        int qr = qrow0 + ty * 4 + r;
        size_t base = (size_t)(b * TT + qr) * (HH * HDD) + h * HDD + tx * 8;
        *reinterpret_cast<float4*>(&att[base]) =
            make_float4(o[r][0]*inv, o[r][1]*inv, o[r][2]*inv, o[r][3]*inv);
        *reinterpret_cast<float4*>(&att[base + 4]) =
            make_float4(o[r][4]*inv, o[r][5]*inv, o[r][6]*inv, o[r][7]*inv);
    }
}

// ---------------------------------------------------------------------------
extern "C" void kernel_launch(void* const* d_in, const int* in_sizes, int n_in,
                              void* d_out, int out_size)
{
    const float* x   = (const float*)d_in[0];
    const float* fc  = (const float*)d_in[1];
    const float* fs  = (const float*)d_in[2];
    // d_in[3] = mask (tril causal) — enforced analytically in flash_kernel
    const float* wq  = (const float*)d_in[4];
    const float* wk  = (const float*)d_in[5];
    const float* wv  = (const float*)d_in[6];
    const float* wo  = (const float*)d_in[7];
    float* out = (float*)d_out;

    float *q, *k, *v, *att;
    cudaGetSymbolAddress((void**)&q,   g_q);
    cudaGetSymbolAddress((void**)&k,   g_k);
    cudaGetSymbolAddress((void**)&v,   g_v);
    cudaGetSymbolAddress((void**)&att, g_att);

    cudaFuncSetAttribute(flash_kernel, cudaFuncAttributeMaxDynamicSharedMemorySize,
                         (int)FLASH_SMEM);

    // Projections
    sgemm_kernel<<<dim3(DD / BN, ROWS / BM), 256>>>(ROWS, DD,            DD, x, wq, q);
    sgemm_kernel<<<dim3((HKK*HDD) / BN, ROWS / BM), 256>>>(ROWS, HKK*HDD, DD, x, wk, k);
    sgemm_kernel<<<dim3((HKK*HDD) / BN, ROWS / BM), 256>>>(ROWS, HKK*HDD, DD, x, wv, v);

    // RoPE
    {
        int totq = ROWS * HH  * (HDD / 2);
        int totk = ROWS * HKK * (HDD / 2);
        rope_kernel<<<(totq + 255) / 256, 256>>>(q, fc, fs, HH,  totq);
        rope_kernel<<<(totk + 255) / 256, 256>>>(k, fc, fs, HKK, totk);
    }

    // Attention
    flash_kernel<<<dim3(TT / BR, HH, BB), 256, FLASH_SMEM>>>(q, k, v, att);

    // Output projection
    sgemm_kernel<<<dim3(DD / BN, ROWS / BM), 256>>>(ROWS, DD, DD, att, wo, out);
}

// round 2
// speedup vs baseline: 3.9360x; 3.9360x over previous
#include <cuda_runtime.h>
#include <math.h>
#include <stdint.h>

#define BB 2
#define TT 2048
#define DD 2048
#define HH 16
#define HKK 4
#define HDD 128
#define REP 4
#define ROWS (BB*TT)   // 4096

// ---------------- scratch (no cudaMalloc allowed) ----------------
__device__ float g_q  [(size_t)ROWS*HH*HDD];   // 32MB
__device__ float g_k  [(size_t)ROWS*HKK*HDD];  // 8MB
__device__ float g_v  [(size_t)ROWS*HKK*HDD];  // 8MB
__device__ float g_att[(size_t)ROWS*HH*HDD];   // 32MB
__device__ float g_xr [(size_t)ROWS*DD];       // 32MB (tf32-rounded x)
__device__ float g_wqr[(size_t)DD*HH*HDD];
__device__ float g_wkr[(size_t)DD*HKK*HDD];
__device__ float g_wvr[(size_t)DD*HKK*HDD];
__device__ float g_wor[(size_t)HH*HDD*DD];

// ---------------- helpers ----------------
__device__ __forceinline__ float rna_tf32(float x) {
    uint32_t u;
    asm("cvt.rna.tf32.f32 %0, %1;" : "=r"(u) : "f"(x));
    return __uint_as_float(u);
}

__device__ __forceinline__ void mma_tf32(float* d, const uint32_t* a, const uint32_t* b) {
    asm volatile(
        "mma.sync.aligned.m16n8k8.row.col.f32.tf32.tf32.f32 "
        "{%0,%1,%2,%3}, {%4,%5,%6,%7}, {%8,%9}, {%0,%1,%2,%3};\n"
        : "+f"(d[0]), "+f"(d[1]), "+f"(d[2]), "+f"(d[3])
        : "r"(a[0]), "r"(a[1]), "r"(a[2]), "r"(a[3]), "r"(b[0]), "r"(b[1]));
}

__device__ __forceinline__ void cp16(uint32_t saddr, const void* g) {
    asm volatile("cp.async.cg.shared.global [%0], [%1], 16;\n" :: "r"(saddr), "l"(g));
}

// ---------------- tf32 rounding prepass ----------------
__global__ void round_tf32_kernel(const float* __restrict__ in, float* __restrict__ out, int n4)
{
    int i = blockIdx.x * blockDim.x + threadIdx.x;
    if (i >= n4) return;
    float4 v = reinterpret_cast<const float4*>(in)[i];
    v.x = rna_tf32(v.x); v.y = rna_tf32(v.y); v.z = rna_tf32(v.z); v.w = rna_tf32(v.w);
    reinterpret_cast<float4*>(out)[i] = v;
}

// ---------------- RoPE (interleaved) + scale + tf32 round ----------------
__global__ void rope_kernel(float* __restrict__ x,
                            const float* __restrict__ cs,
                            const float* __restrict__ sn,
                            int nh, int total, float scale)
{
    int idx = blockIdx.x * blockDim.x + threadIdx.x;
    if (idx >= total) return;
    int i    = idx % (HDD / 2);
    int rest = idx / (HDD / 2);
    int h    = rest % nh;
    int row  = rest / nh;
    int t    = row % TT;
    float c = cs[t * (HDD / 2) + i];
    float s = sn[t * (HDD / 2) + i];
    float* p = x + ((size_t)row * nh + h) * HDD + 2 * i;
    float xr = p[0], xi = p[1];
    p[0] = rna_tf32((xr * c - xi * s) * scale);
    p[1] = rna_tf32((xr * s + xi * c) * scale);
}

// ---------------------------------------------------------------------------
// TF32 tensor-core GEMM: C[M,N] = A[M,K] @ B[K,N], row-major fp32 (tf32 bits).
// Block 128x128, BK=32, 8 warps (2x4), warp tile 64x32, cp.async 3-stage.
// ---------------------------------------------------------------------------
#define GA_STR 36
#define GB_STR 136
#define GSTAGE_FLOATS (128*GA_STR + 32*GB_STR)   // 4608 + 4352 = 8960
#define GEMM_SMEM (GSTAGE_FLOATS*3*4)            // 107520 bytes

__global__ void __launch_bounds__(256, 2) gemm_tc(
    int M, int N, int K,
    const float* __restrict__ A,
    const float* __restrict__ B0, float* __restrict__ C0,
    const float* __restrict__ B1, float* __restrict__ C1,
    int do_round)
{
    const float* B = (blockIdx.z == 0) ? B0 : B1;
    float*       C = (blockIdx.z == 0) ? C0 : C1;

    extern __shared__ float sm[];
    const int tid  = threadIdx.x;
    const int lane = tid & 31;
    const int wid  = tid >> 5;
    const int wm   = wid >> 2;    // 0..1
    const int wn   = wid & 3;     // 0..3
    const int rowBase = blockIdx.y * 128;
    const int colBase = blockIdx.x * 128;
    const uint32_t smem_base = (uint32_t)__cvta_generic_to_shared(sm);

    float acc[4][4][4];
    #pragma unroll
    for (int mt = 0; mt < 4; mt++)
        #pragma unroll
        for (int nt = 0; nt < 4; nt++)
            #pragma unroll
            for (int j = 0; j < 4; j++) acc[mt][nt][j] = 0.0f;

    const int nslab = K / 32;

    auto issue = [&](int s) {
        int k0 = s * 32;
        uint32_t sa = smem_base + (uint32_t)((s % 3) * GSTAGE_FLOATS) * 4u;
        uint32_t sb = sa + 128u * GA_STR * 4u;
        #pragma unroll
        for (int i = 0; i < 4; i++) {
            int idx = tid + i * 256;
            int r = idx >> 3, c = idx & 7;
            cp16(sa + (uint32_t)(r * GA_STR + c * 4) * 4u,
                 A + (size_t)(rowBase + r) * K + k0 + c * 4);
        }
        #pragma unroll
        for (int i = 0; i < 4; i++) {
            int idx = tid + i * 256;
            int r = idx >> 5, c = idx & 31;
            cp16(sb + (uint32_t)(r * GB_STR + c * 4) * 4u,
                 B + (size_t)(k0 + r) * N + colBase + c * 4);
        }
        asm volatile("cp.async.commit_group;\n" ::: "memory");
    };

    issue(0);
    issue(1);

    for (int s = 0; s < nslab; s++) {
        asm volatile("cp.async.wait_group 1;\n" ::: "memory");
        __syncthreads();
        if (s + 2 < nslab) issue(s + 2);

        const float* As_ = sm + (s % 3) * GSTAGE_FLOATS;
        const float* Bs_ = As_ + 128 * GA_STR;

        #pragma unroll
        for (int k8 = 0; k8 < 4; k8++) {
            const int kb = k8 * 8;
            uint32_t a[4][2][2], bfr[4][2];
            #pragma unroll
            for (int mt = 0; mt < 4; mt++) {
                int r = wm * 64 + mt * 16 + (lane >> 2);
                a[mt][0][0] = __float_as_uint(As_[r * GA_STR + kb + (lane & 3)]);
                a[mt][0][1] = __float_as_uint(As_[(r + 8) * GA_STR + kb + (lane & 3)]);
                a[mt][1][0] = __float_as_uint(As_[r * GA_STR + kb + 4 + (lane & 3)]);
                a[mt][1][1] = __float_as_uint(As_[(r + 8) * GA_STR + kb + 4 + (lane & 3)]);
            }
            #pragma unroll
            for (int nt = 0; nt < 4; nt++) {
                int cix = wn * 32 + nt * 8 + (lane >> 2);
                bfr[nt][0] = __float_as_uint(Bs_[(kb + (lane & 3)) * GB_STR + cix]);
                bfr[nt][1] = __float_as_uint(Bs_[(kb + 4 + (lane & 3)) * GB_STR + cix]);
            }
            #pragma unroll
            for (int mt = 0; mt < 4; mt++) {
                uint32_t av[4] = { a[mt][0][0], a[mt][0][1], a[mt][1][0], a[mt][1][1] };
                #pragma unroll
                for (int nt = 0; nt < 4; nt++)
                    mma_tf32(acc[mt][nt], av, bfr[nt]);
            }
        }
        __syncthreads();
    }

    #pragma unroll
    for (int mt = 0; mt < 4; mt++) {
        int r0 = rowBase + wm * 64 + mt * 16 + (lane >> 2);
        #pragma unroll
        for (int nt = 0; nt < 4; nt++) {
            int c0 = colBase + wn * 32 + nt * 8 + 2 * (lane & 3);
            float v0 = acc[mt][nt][0], v1 = acc[mt][nt][1];
            float v2 = acc[mt][nt][2], v3 = acc[mt][nt][3];
            if (do_round) {
                v0 = rna_tf32(v0); v1 = rna_tf32(v1);
                v2 = rna_tf32(v2); v3 = rna_tf32(v3);
            }
            *reinterpret_cast<float2*>(&C[(size_t)r0 * N + c0])       = make_float2(v0, v1);
            *reinterpret_cast<float2*>(&C[(size_t)(r0 + 8) * N + c0]) = make_float2(v2, v3);
        }
    }
}

// ---------------------------------------------------------------------------
// Tensor-core flash attention, tf32 mma, causal. BR=128, BC=64, 8 warps.
// Each warp owns 16 q-rows -> softmax never crosses warps.
// Inputs q,k,v already tf32-rounded (q also pre-scaled by 1/sqrt(HD)).
// ---------------------------------------------------------------------------
#define FQ_STR 132
#define FK_STR 132
#define FV_STR 136
#define FP_STR 68
#define FLASH_SMEM ((128*FQ_STR + 64*FK_STR + 64*FV_STR + 128*FP_STR)*4)  // 171008

__global__ void __launch_bounds__(256, 1) flash_tc(
    const float* __restrict__ q, const float* __restrict__ k,
    const float* __restrict__ v, float* __restrict__ att)
{
    extern __shared__ float sm[];
    float* Qs = sm;
    float* Ks = Qs + 128 * FQ_STR;
    float* Vs = Ks + 64 * FK_STR;
    float* Ps = Vs + 64 * FV_STR;

    const int tid  = threadIdx.x;
    const int lane = tid & 31;
    const int wid  = tid >> 5;
    const int bx = blockIdx.x, h = blockIdx.y, b = blockIdx.z;
    const int hk = h / REP;
    const int qrow0 = bx * 128;

    // cooperative Q load
    {
        const float* qg = q + ((size_t)(b * TT + qrow0) * HH + h) * HDD;
        #pragma unroll
        for (int i = 0; i < 16; i++) {
            int idx = tid + i * 256;
            int r = idx >> 5, c = idx & 31;
            *reinterpret_cast<float4*>(&Qs[r * FQ_STR + c * 4]) =
                *reinterpret_cast<const float4*>(&qg[(size_t)r * HH * HDD + c * 4]);
        }
    }
    __syncthreads();

    // cache Q fragments in registers for all 16 k-steps
    uint32_t qa[16][4];
    {
        const int r = wid * 16 + (lane >> 2);
        #pragma unroll
        for (int ks = 0; ks < 16; ks++) {
            int cc = ks * 8 + (lane & 3);
            qa[ks][0] = __float_as_uint(Qs[r * FQ_STR + cc]);
            qa[ks][1] = __float_as_uint(Qs[(r + 8) * FQ_STR + cc]);
            qa[ks][2] = __float_as_uint(Qs[r * FQ_STR + cc + 4]);
            qa[ks][3] = __float_as_uint(Qs[(r + 8) * FQ_STR + cc + 4]);
        }
    }

    float o[16][4];
    #pragma unroll
    for (int nt = 0; nt < 16; nt++)
        #pragma unroll
        for (int j = 0; j < 4; j++) o[nt][j] = 0.0f;

    float m0 = -INFINITY, m1 = -INFINITY, l0 = 0.0f, l1 = 0.0f;
    const int r0g = qrow0 + wid * 16 + (lane >> 2);
    const int r1g = r0g + 8;
    const int rloc = wid * 16 + (lane >> 2);

    const int ntile = 2 * bx + 2;
    for (int kt = 0; kt < ntile; kt++) {
        __syncthreads();
        {
            const float* kg = k + ((size_t)(b * TT + kt * 64) * HKK + hk) * HDD;
            const float* vg = v + ((size_t)(b * TT + kt * 64) * HKK + hk) * HDD;
            #pragma unroll
            for (int i = 0; i < 8; i++) {
                int idx = tid + i * 256;
                int r = idx >> 5, c = idx & 31;
                *reinterpret_cast<float4*>(&Ks[r * FK_STR + c * 4]) =
                    *reinterpret_cast<const float4*>(&kg[(size_t)r * HKK * HDD + c * 4]);
                *reinterpret_cast<float4*>(&Vs[r * FV_STR + c * 4]) =
                    *reinterpret_cast<const float4*>(&vg[(size_t)r * HKK * HDD + c * 4]);
            }
        }
        __syncthreads();

        // S = Q K^T   (16 x 64 per warp)
        float s[8][4];
        #pragma unroll
        for (int nt = 0; nt < 8; nt++)
            #pragma unroll
            for (int j = 0; j < 4; j++) s[nt][j] = 0.0f;

        #pragma unroll
        for (int ks = 0; ks < 16; ks++) {
            #pragma unroll
            for (int nt = 0; nt < 8; nt++) {
                uint32_t bb[2];
                int n = nt * 8 + (lane >> 2);
                int c = ks * 8 + (lane & 3);
                bb[0] = __float_as_uint(Ks[n * FK_STR + c]);
                bb[1] = __float_as_uint(Ks[n * FK_STR + c + 4]);
                mma_tf32(s[nt], qa[ks], bb);
            }
        }

        // causal mask (only last two tiles of each block need it)
        if (kt >= 2 * bx) {
            #pragma unroll
            for (int nt = 0; nt < 8; nt++) {
                int c0 = kt * 64 + nt * 8 + 2 * (lane & 3);
                if (c0     > r0g) s[nt][0] = -INFINITY;
                if (c0 + 1 > r0g) s[nt][1] = -INFINITY;
                if (c0     > r1g) s[nt][2] = -INFINITY;
                if (c0 + 1 > r1g) s[nt][3] = -INFINITY;
            }
        }

        // online softmax (rows r0g, r1g; 4 lanes share a row)
        float mx0 = -INFINITY, mx1 = -INFINITY;
        #pragma unroll
        for (int nt = 0; nt < 8; nt++) {
            mx0 = fmaxf(mx0, fmaxf(s[nt][0], s[nt][1]));
            mx1 = fmaxf(mx1, fmaxf(s[nt][2], s[nt][3]));
        }
        mx0 = fmaxf(mx0, __shfl_xor_sync(0xffffffffu, mx0, 1));
        mx0 = fmaxf(mx0, __shfl_xor_sync(0xffffffffu, mx0, 2));
        mx1 = fmaxf(mx1, __shfl_xor_sync(0xffffffffu, mx1, 1));
        mx1 = fmaxf(mx1, __shfl_xor_sync(0xffffffffu, mx1, 2));

        float nm0 = fmaxf(m0, mx0), nm1 = fmaxf(m1, mx1);
        float al0 = __expf(m0 - nm0), al1 = __expf(m1 - nm1);
        m0 = nm0; m1 = nm1;

        float ps0 = 0.0f, ps1 = 0.0f;
        #pragma unroll
        for (int nt = 0; nt < 8; nt++) {
            float p0 = rna_tf32(__expf(s[nt][0] - nm0));
            float p1 = rna_tf32(__expf(s[nt][1] - nm0));
            float p2 = rna_tf32(__expf(s[nt][2] - nm1));
            float p3 = rna_tf32(__expf(s[nt][3] - nm1));
            ps0 += p0 + p1;
            ps1 += p2 + p3;
            int cc = nt * 8 + 2 * (lane & 3);
            *reinterpret_cast<float2*>(&Ps[rloc * FP_STR + cc])       = make_float2(p0, p1);
            *reinterpret_cast<float2*>(&Ps[(rloc + 8) * FP_STR + cc]) = make_float2(p2, p3);
        }
        ps0 += __shfl_xor_sync(0xffffffffu, ps0, 1);
        ps0 += __shfl_xor_sync(0xffffffffu, ps0, 2);
        ps1 += __shfl_xor_sync(0xffffffffu, ps1, 1);
        ps1 += __shfl_xor_sync(0xffffffffu, ps1, 2);
        l0 = l0 * al0 + ps0;
        l1 = l1 * al1 + ps1;

        #pragma unroll
        for (int nt = 0; nt < 16; nt++) {
            o[nt][0] *= al0; o[nt][1] *= al0;
            o[nt][2] *= al1; o[nt][3] *= al1;
        }
        __syncwarp();

        // O += P @ V   (16 x 128 per warp)
        #pragma unroll
        for (int ks2 = 0; ks2 < 8; ks2++) {
            uint32_t pa[4];
            int cc = ks2 * 8 + (lane & 3);
            pa[0] = __float_as_uint(Ps[rloc * FP_STR + cc]);
            pa[1] = __float_as_uint(Ps[(rloc + 8) * FP_STR + cc]);
            pa[2] = __float_as_uint(Ps[rloc * FP_STR + cc + 4]);
            pa[3] = __float_as_uint(Ps[(rloc + 8) * FP_STR + cc + 4]);
            #pragma unroll
            for (int nt2 = 0; nt2 < 16; nt2++) {
                uint32_t vb[2];
                int n  = nt2 * 8 + (lane >> 2);
                int kk = ks2 * 8 + (lane & 3);
                vb[0] = __float_as_uint(Vs[kk * FV_STR + n]);
                vb[1] = __float_as_uint(Vs[(kk + 4) * FV_STR + n]);
                mma_tf32(o[nt2], pa, vb);
            }
        }
        __syncwarp();
    }

    // epilogue: normalize, tf32-round (consumed by final TC GEMM), store
    const float inv0 = 1.0f / l0, inv1 = 1.0f / l1;
    #pragma unroll
    for (int nt2 = 0; nt2 < 16; nt2++) {
        int c = h * HDD + nt2 * 8 + 2 * (lane & 3);
        size_t base0 = (size_t)(b * TT + r0g) * (HH * HDD) + c;
        size_t base1 = (size_t)(b * TT + r1g) * (HH * HDD) + c;
        *reinterpret_cast<float2*>(&att[base0]) =
            make_float2(rna_tf32(o[nt2][0] * inv0), rna_tf32(o[nt2][1] * inv0));
        *reinterpret_cast<float2*>(&att[base1]) =
            make_float2(rna_tf32(o[nt2][2] * inv1), rna_tf32(o[nt2][3] * inv1));
    }
}

// ---------------------------------------------------------------------------
extern "C" void kernel_launch(void* const* d_in, const int* in_sizes, int n_in,
                              void* d_out, int out_size)
{
    const float* x  = (const float*)d_in[0];
    const float* fc = (const float*)d_in[1];
    const float* fs = (const float*)d_in[2];
    // d_in[3] = mask — enforced analytically
    const float* wq = (const float*)d_in[4];
    const float* wk = (const float*)d_in[5];
    const float* wv = (const float*)d_in[6];
    const float* wo = (const float*)d_in[7];
    float* out = (float*)d_out;

    float *q, *k, *v, *att, *xr, *wqr, *wkr, *wvr, *wor;
    cudaGetSymbolAddress((void**)&q,   g_q);
    cudaGetSymbolAddress((void**)&k,   g_k);
    cudaGetSymbolAddress((void**)&v,   g_v);
    cudaGetSymbolAddress((void**)&att, g_att);
    cudaGetSymbolAddress((void**)&xr,  g_xr);
    cudaGetSymbolAddress((void**)&wqr, g_wqr);
    cudaGetSymbolAddress((void**)&wkr, g_wkr);
    cudaGetSymbolAddress((void**)&wvr, g_wvr);
    cudaGetSymbolAddress((void**)&wor, g_wor);

    cudaFuncSetAttribute(gemm_tc,  cudaFuncAttributeMaxDynamicSharedMemorySize, GEMM_SMEM);
    cudaFuncSetAttribute(flash_tc, cudaFuncAttributeMaxDynamicSharedMemorySize, (int)FLASH_SMEM);

    // 1) tf32-round inputs (HMMA truncates; pre-rounding removes the bias)
    round_tf32_kernel<<<(ROWS*DD/4 + 255)/256, 256>>>(x,  xr,  ROWS*DD/4);
    round_tf32_kernel<<<(DD*HH*HDD/4 + 255)/256, 256>>>(wq, wqr, DD*HH*HDD/4);
    round_tf32_kernel<<<(DD*HKK*HDD/4 + 255)/256, 256>>>(wk, wkr, DD*HKK*HDD/4);
    round_tf32_kernel<<<(DD*HKK*HDD/4 + 255)/256, 256>>>(wv, wvr, DD*HKK*HDD/4);
    round_tf32_kernel<<<(HH*HDD*DD/4 + 255)/256, 256>>>(wo, wor, HH*HDD*DD/4);

    // 2) projections
    gemm_tc<<<dim3(DD/128, ROWS/128, 1), 256, GEMM_SMEM>>>(
        ROWS, DD, DD, xr, wqr, q, nullptr, nullptr, 0);
    gemm_tc<<<dim3(HKK*HDD/128, ROWS/128, 2), 256, GEMM_SMEM>>>(
        ROWS, HKK*HDD, DD, xr, wkr, k, wvr, v, 1);   // rounds v (and k; k re-rounded by rope)

    // 3) RoPE (+ fold 1/sqrt(HD) into q) with tf32 rounding
    {
        int totq = ROWS * HH  * (HDD / 2);
        int totk = ROWS * HKK * (HDD / 2);
        rope_kernel<<<(totq + 255)/256, 256>>>(q, fc, fs, HH,  totq, 0.08838834764831845f);
        rope_kernel<<<(totk + 255)/256, 256>>>(k, fc, fs, HKK, totk, 1.0f);
    }

    // 4) tensor-core flash attention
    flash_tc<<<dim3(TT/128, HH, BB), 256, FLASH_SMEM>>>(q, k, v, att);

    // 5) output projection (fp32 accum, unrounded output)
    gemm_tc<<<dim3(DD/128, ROWS/128, 1), 256, GEMM_SMEM>>>(
        ROWS, DD, HH*HDD, att, wor, out, nullptr, nullptr, 0);
}